// round 8
// baseline (speedup 1.0000x reference)
#include <cuda_runtime.h>
#include <cstdint>

#define MTOT  8192
#define DIN   2048
#define DOUT  2048
#define GROUP 32
#define NG    64

// GEMM tiling: 128x128 CTA tile, 8 warps (2x4), warp tile 64x32, int8 IMMA
#define BM 128
#define BN 128
#define BKB 64                 // k-bytes per chunk (int8) = 2 groups = 2 immas deep
#define STAGES 3
#define NKT (DIN / BKB)        // 32
#define PITCHB 80              // bytes per smem row (conflict-free 16B phases)
#define TILE_B (128 * PITCHB)        // 10240 per operand per stage
#define STAGE_B (2 * TILE_B)         // 20480
#define SC_PITCH 68                  // floats per scale row (padded: bank-stride 4)
#define SC_BYTES (128 * SC_PITCH * 4)     // 34816
#define SMEM_TOTAL (SC_BYTES + STAGES * STAGE_B)  // 96256

// Scratch (allocation-free rule: __device__ globals)
__device__ int8_t g_Aq[(size_t)MTOT * DIN];   // per-token int8 q
__device__ int8_t g_Wq[(size_t)DOUT * DIN];   // raw int4 weights as int8
__device__ float2 g_sz[MTOT];                 // (scale, zp) per token
__device__ float  g_colsum[DOUT];             // sum_g s_g*(sum_g w - 32 z_g)

// ---------------------------------------------------------------------------
__device__ __forceinline__ void cp_async16(uint32_t saddr, const void* gaddr) {
    asm volatile("cp.async.cg.shared.global [%0], [%1], 16;\n" :: "r"(saddr), "l"(gaddr));
}
__device__ __forceinline__ void cp_commit() { asm volatile("cp.async.commit_group;\n" ::: "memory"); }
template <int N>
__device__ __forceinline__ void cp_wait() { asm volatile("cp.async.wait_group %0;\n" :: "n"(N) : "memory"); }

// ---------------------------------------------------------------------------
// Kernel 1: per-token asymmetric int8 fake-quant of x. Stores q (int8 packed),
// and (scale, zp) per token. (q - zp) is applied exactly in the GEMM epilogue.
// ---------------------------------------------------------------------------
__global__ void quant_x_kernel(const float4* __restrict__ x) {
    const int token = blockIdx.x;
    const float4* xr = x + (size_t)token * (DIN / 4);
    const int tid = threadIdx.x;  // 256 threads

    float4 v0 = xr[tid];
    float4 v1 = xr[tid + 256];
    float vmin = fminf(fminf(fminf(v0.x, v0.y), fminf(v0.z, v0.w)),
                       fminf(fminf(v1.x, v1.y), fminf(v1.z, v1.w)));
    float vmax = fmaxf(fmaxf(fmaxf(v0.x, v0.y), fmaxf(v0.z, v0.w)),
                       fmaxf(fmaxf(v1.x, v1.y), fmaxf(v1.z, v1.w)));
    vmin = fminf(vmin, 0.0f);
    vmax = fmaxf(vmax, 0.0f);
#pragma unroll
    for (int off = 16; off > 0; off >>= 1) {
        vmin = fminf(vmin, __shfl_xor_sync(0xffffffffu, vmin, off));
        vmax = fmaxf(vmax, __shfl_xor_sync(0xffffffffu, vmax, off));
    }
    __shared__ float smin[8], smax[8];
    if ((tid & 31) == 0) { smin[tid >> 5] = vmin; smax[tid >> 5] = vmax; }
    __syncthreads();
    float bmin = smin[0], bmax = smax[0];
#pragma unroll
    for (int i = 1; i < 8; i++) { bmin = fminf(bmin, smin[i]); bmax = fmaxf(bmax, smax[i]); }

    float scale = (bmax - bmin) / 255.0f;
    scale = fmaxf(scale, 1.1920928955078125e-07f);  // jnp.finfo(f32).eps
    float inv = 1.0f / scale;
    float zp = fminf(fmaxf(-128.0f - rintf(bmin * inv), -128.0f), 127.0f);
    if (tid == 0) g_sz[token] = make_float2(scale, zp);

#define QI(f) ((int)(fminf(fmaxf(rintf((f) * inv) + zp, -128.0f), 127.0f)))
    uint32_t p0, p1;
    {
        int q0 = QI(v0.x), q1 = QI(v0.y), q2 = QI(v0.z), q3 = QI(v0.w);
        p0 = (q0 & 0xFF) | ((q1 & 0xFF) << 8) | ((q2 & 0xFF) << 16) | ((q3 & 0xFF) << 24);
        q0 = QI(v1.x); q1 = QI(v1.y); q2 = QI(v1.z); q3 = QI(v1.w);
        p1 = (q0 & 0xFF) | ((q1 & 0xFF) << 8) | ((q2 & 0xFF) << 16) | ((q3 & 0xFF) << 24);
    }
#undef QI
    uint32_t* aw = (uint32_t*)(g_Aq + (size_t)token * DIN);
    aw[tid] = p0;
    aw[tid + 256] = p1;
}

// ---------------------------------------------------------------------------
// Kernel 2: weight repack int32 -> int8 + per-row colsum.
// One block per output row o.
// ---------------------------------------------------------------------------
__global__ void wprep_kernel(const int4* __restrict__ w_int,
                             const float* __restrict__ ws,
                             const float* __restrict__ wz) {
    const int o = blockIdx.x;
    const int t = threadIdx.x;  // 256; covers k = 8t..8t+7
    const int4* wr = w_int + (size_t)o * (DIN / 4) + t * 2;
    int4 a = wr[0], b = wr[1];

    uint32_t p0 = (a.x & 0xFF) | ((a.y & 0xFF) << 8) | ((a.z & 0xFF) << 16) | ((a.w & 0xFF) << 24);
    uint32_t p1 = (b.x & 0xFF) | ((b.y & 0xFF) << 8) | ((b.z & 0xFF) << 16) | ((b.w & 0xFF) << 24);
    ((uint2*)(g_Wq + (size_t)o * DIN))[t] = make_uint2(p0, p1);

    int s8 = a.x + a.y + a.z + a.w + b.x + b.y + b.z + b.w;
    s8 += __shfl_xor_sync(0xffffffffu, s8, 1);
    s8 += __shfl_xor_sync(0xffffffffu, s8, 2);   // now sum over group of 32

    __shared__ float part[64];
    if ((t & 3) == 0) {
        const int g = t >> 2;
        part[g] = ws[o * NG + g] * ((float)s8 - 32.0f * wz[o * NG + g]);
    }
    __syncthreads();
    if (t < 32) {
        float v = part[t] + part[t + 32];
#pragma unroll
        for (int off = 16; off > 0; off >>= 1)
            v += __shfl_xor_sync(0xffffffffu, v, off);
        if (t == 0) g_colsum[o] = v;
    }
}

// ---------------------------------------------------------------------------
// Kernel 3: int8 grouped GEMM.
// out[m,n] = s_x[m] * ( sum_g s_w[n,g]*S_g(m,n) - zp[m]*colsum[n] )
// 128x128 CTA tile, 8 warps, warp tile 64x32, mma.m16n8k32.s8 per group,
// per-group fp32 scale-accumulate (I2F+FFMA), 3-stage cp.async wait_group 1.
// ---------------------------------------------------------------------------
extern __shared__ char dsmem[];

__global__ void gemm_kernel(float* __restrict__ out, const float* __restrict__ ws) {
    const int tid  = threadIdx.x;      // 256
    const int lane = tid & 31;
    const int wid  = tid >> 5;
    const int warp_m = wid >> 2;       // 0..1  -> 64 rows
    const int warp_n = wid & 3;        // 0..3  -> 32 cols
    const int bn = blockIdx.x, bm = blockIdx.y;

    const int8_t* Aq = g_Aq + (size_t)(bm * BM) * DIN;
    const int8_t* Wq = g_Wq + (size_t)(bn * BN) * DIN;

    const uint32_t sb = (uint32_t)__cvta_generic_to_shared(dsmem);
    const uint32_t tiles = sb + SC_BYTES;
    float* sws = (float*)dsmem;        // [128 cols][SC_PITCH] group scales

    // -- preload w_scales for this CTA's 128 cols (coalesced, row-major copy) --
#pragma unroll
    for (int i = 0; i < 8; i++) {
        const int idx = tid + i * 256;           // 2048 float4s
        const int c = idx >> 4, f4 = idx & 15;
        cp_async16(sb + (uint32_t)(c * SC_PITCH + f4 * 4) * 4,
                   ws + (size_t)(bn * BN + c) * NG + f4 * 4);
    }

    auto load_stage = [&](int s, int kt) {
        const uint32_t aB = tiles + s * STAGE_B;
        const uint32_t bB = aB + TILE_B;
        const int kb = kt * BKB;
#pragma unroll
        for (int j = 0; j < 2; j++) {
            const int c = tid + j * 256;
            const int r = c >> 2, off = (c & 3) * 16;
            cp_async16(aB + (uint32_t)(r * PITCHB + off), Aq + (size_t)r * DIN + kb + off);
            cp_async16(bB + (uint32_t)(r * PITCHB + off), Wq + (size_t)r * DIN + kb + off);
        }
        cp_commit();
    };

    load_stage(0, 0);   // commit also covers the scale cp.asyncs above
    load_stage(1, 1);

    float acc[4][4][4];
#pragma unroll
    for (int i = 0; i < 4; i++)
#pragma unroll
        for (int j = 0; j < 4; j++)
#pragma unroll
            for (int r = 0; r < 4; r++) acc[i][j][r] = 0.0f;

    // ldmatrix per-lane offsets (byte units, int8)
    const int a_row  = warp_m * 64 + (lane & 15);
    const int a_koff = (lane >> 4) * 16;
    const int b_row  = warp_n * 32 + (lane & 7) + ((lane >> 4) & 1) * 8;
    const int b_koff = ((lane >> 3) & 1) * 16;
    const int sc_col = warp_n * 32 + (lane & 3) * 2;

    int s_cur = 0, s_nxt = 2;
#pragma unroll 1
    for (int kt = 0; kt < NKT; kt++) {
        if (kt + 1 < NKT) cp_wait<1>(); else cp_wait<0>();
        __syncthreads();
        if (kt + 2 < NKT) load_stage(s_nxt, kt + 2);

        const uint32_t aBase = tiles + s_cur * STAGE_B;
        const uint32_t bBase = aBase + TILE_B;
        s_nxt = s_cur;
        s_cur = (s_cur == 2) ? 0 : s_cur + 1;

#pragma unroll
        for (int ks = 0; ks < 2; ks++) {          // one group (K=32) per step
            const int g = kt * 2 + ks;
            uint32_t af[4][4];
#pragma unroll
            for (int mt = 0; mt < 4; mt++) {
                uint32_t addr = aBase +
                    (uint32_t)((a_row + mt * 16) * PITCHB + ks * 32 + a_koff);
                asm volatile(
                    "ldmatrix.sync.aligned.m8n8.x4.shared.b16 {%0,%1,%2,%3}, [%4];"
                    : "=r"(af[mt][0]), "=r"(af[mt][1]), "=r"(af[mt][2]), "=r"(af[mt][3])
                    : "r"(addr));
            }
            uint32_t bf[4][2];
#pragma unroll
            for (int p = 0; p < 2; p++) {
                uint32_t addr = bBase +
                    (uint32_t)((b_row + p * 16) * PITCHB + ks * 32 + b_koff);
                uint32_t r0, r1, r2, r3;
                asm volatile(
                    "ldmatrix.sync.aligned.m8n8.x4.shared.b16 {%0,%1,%2,%3}, [%4];"
                    : "=r"(r0), "=r"(r1), "=r"(r2), "=r"(r3)
                    : "r"(addr));
                bf[2 * p][0] = r0; bf[2 * p][1] = r1;
                bf[2 * p + 1][0] = r2; bf[2 * p + 1][1] = r3;
            }
            // group scales for this lane's 2 columns x 4 n-tiles
            float s0[4], s1[4];
#pragma unroll
            for (int nt = 0; nt < 4; nt++) {
                const int c0 = sc_col + nt * 8;
                s0[nt] = sws[c0 * SC_PITCH + g];
                s1[nt] = sws[(c0 + 1) * SC_PITCH + g];
            }
#pragma unroll
            for (int mt = 0; mt < 4; mt++)
#pragma unroll
                for (int nt = 0; nt < 4; nt++) {
                    int d0, d1, d2, d3;
                    asm volatile(
                        "mma.sync.aligned.m16n8k32.row.col.s32.s8.s8.s32 "
                        "{%0,%1,%2,%3}, {%4,%5,%6,%7}, {%8,%9}, {%10,%11,%12,%13};"
                        : "=r"(d0), "=r"(d1), "=r"(d2), "=r"(d3)
                        : "r"(af[mt][0]), "r"(af[mt][1]), "r"(af[mt][2]), "r"(af[mt][3]),
                          "r"(bf[nt][0]), "r"(bf[nt][1]),
                          "r"(0), "r"(0), "r"(0), "r"(0));
                    acc[mt][nt][0] += s0[nt] * (float)d0;   // exact: |d| < 2^24
                    acc[mt][nt][1] += s1[nt] * (float)d1;
                    acc[mt][nt][2] += s0[nt] * (float)d2;
                    acc[mt][nt][3] += s1[nt] * (float)d3;
                }
        }
    }

    // Epilogue: out = s_x*(acc - zp*colsum)
    const int gm0 = bm * BM + warp_m * 64 + (lane >> 2);
    const int gn0 = bn * BN + warp_n * 32 + (lane & 3) * 2;
#pragma unroll
    for (int mt = 0; mt < 4; mt++) {
        const int r0 = gm0 + mt * 16;
        const float2 sz0 = g_sz[r0];
        const float2 sz1 = g_sz[r0 + 8];
#pragma unroll
        for (int nt = 0; nt < 4; nt++) {
            const int c = gn0 + nt * 8;
            const float2 cs = *(const float2*)&g_colsum[c];
            float2 v0 = make_float2(sz0.x * (acc[mt][nt][0] - sz0.y * cs.x),
                                    sz0.x * (acc[mt][nt][1] - sz0.y * cs.y));
            float2 v1 = make_float2(sz1.x * (acc[mt][nt][2] - sz1.y * cs.x),
                                    sz1.x * (acc[mt][nt][3] - sz1.y * cs.y));
            *(float2*)&out[(size_t)r0 * DOUT + c] = v0;
            *(float2*)&out[(size_t)(r0 + 8) * DOUT + c] = v1;
        }
    }
}

// ---------------------------------------------------------------------------
extern "C" void kernel_launch(void* const* d_in, const int* in_sizes, int n_in,
                              void* d_out, int out_size) {
    (void)in_sizes; (void)n_in; (void)out_size;
    const float* x      = (const float*)d_in[0];
    const int*   w_int  = (const int*)d_in[1];
    const float* w_sc   = (const float*)d_in[2];
    const float* w_zp   = (const float*)d_in[3];
    float* out = (float*)d_out;

    cudaFuncSetAttribute(gemm_kernel, cudaFuncAttributeMaxDynamicSharedMemorySize, SMEM_TOTAL);

    quant_x_kernel<<<MTOT, 256>>>((const float4*)x);
    wprep_kernel<<<DOUT, 256>>>((const int4*)w_int, w_sc, w_zp);
    gemm_kernel<<<dim3(DOUT / BN, MTOT / BM), 256, SMEM_TOTAL>>>(out, w_sc);
}

// round 9
// speedup vs baseline: 1.0189x; 1.0189x over previous
#include <cuda_runtime.h>
#include <cstdint>

#define MTOT  8192
#define DIN   2048
#define DOUT  2048
#define GROUP 32
#define NG    64

// GEMM tiling: 128x128 CTA tile, 8 warps (2x4), warp tile 64x32, int8 IMMA
#define BM 128
#define BN 128
#define BKB 64                 // k-bytes per chunk (int8) = 2 groups deep
#define STAGES 3
#define NKT (DIN / BKB)        // 32
#define PITCHB 80              // bytes per smem row (conflict-free 16B phases)
#define TILE_B (128 * PITCHB)        // 10240 per operand per stage
#define STAGE_B (2 * TILE_B)         // 20480
#define SC_PITCH2 66                 // float2 per colpair row (pad: bank-shift 4)
#define SC_BYTES (64 * SC_PITCH2 * 8)     // 33792
#define SMEM_TOTAL (SC_BYTES + STAGES * STAGE_B)  // 95232

#define MAGICI 0x4B400000                     // int bits of 12582912.0f
#define NEGB2  0xCB400000CB400000ULL          // packed (-12582912.f, -12582912.f)

// Scratch (allocation-free rule: __device__ globals)
__device__ int8_t g_Aq[(size_t)MTOT * DIN];   // per-token int8 q
__device__ int8_t g_Wq[(size_t)DOUT * DIN];   // raw int4 weights as int8
__device__ float2 g_sz[MTOT];                 // (scale, zp) per token
__device__ float  g_colsum[DOUT];             // sum_g s_g*(sum_g w - 32 z_g)

// ---------------------------------------------------------------------------
__device__ __forceinline__ void cp_async16(uint32_t saddr, const void* gaddr) {
    asm volatile("cp.async.cg.shared.global [%0], [%1], 16;\n" :: "r"(saddr), "l"(gaddr));
}
__device__ __forceinline__ void cp_commit() { asm volatile("cp.async.commit_group;\n" ::: "memory"); }
template <int N>
__device__ __forceinline__ void cp_wait() { asm volatile("cp.async.wait_group %0;\n" :: "n"(N) : "memory"); }

// ---------------------------------------------------------------------------
// Kernel 1: per-token asymmetric int8 fake-quant of x. Stores q (int8 packed),
// and (scale, zp) per token. (q - zp) is applied exactly in the GEMM epilogue.
// ---------------------------------------------------------------------------
__global__ void quant_x_kernel(const float4* __restrict__ x) {
    const int token = blockIdx.x;
    const float4* xr = x + (size_t)token * (DIN / 4);
    const int tid = threadIdx.x;  // 256 threads

    float4 v0 = xr[tid];
    float4 v1 = xr[tid + 256];
    float vmin = fminf(fminf(fminf(v0.x, v0.y), fminf(v0.z, v0.w)),
                       fminf(fminf(v1.x, v1.y), fminf(v1.z, v1.w)));
    float vmax = fmaxf(fmaxf(fmaxf(v0.x, v0.y), fmaxf(v0.z, v0.w)),
                       fmaxf(fmaxf(v1.x, v1.y), fmaxf(v1.z, v1.w)));
    vmin = fminf(vmin, 0.0f);
    vmax = fmaxf(vmax, 0.0f);
#pragma unroll
    for (int off = 16; off > 0; off >>= 1) {
        vmin = fminf(vmin, __shfl_xor_sync(0xffffffffu, vmin, off));
        vmax = fmaxf(vmax, __shfl_xor_sync(0xffffffffu, vmax, off));
    }
    __shared__ float smin[8], smax[8];
    if ((tid & 31) == 0) { smin[tid >> 5] = vmin; smax[tid >> 5] = vmax; }
    __syncthreads();
    float bmin = smin[0], bmax = smax[0];
#pragma unroll
    for (int i = 1; i < 8; i++) { bmin = fminf(bmin, smin[i]); bmax = fmaxf(bmax, smax[i]); }

    float scale = (bmax - bmin) / 255.0f;
    scale = fmaxf(scale, 1.1920928955078125e-07f);  // jnp.finfo(f32).eps
    float inv = 1.0f / scale;
    float zp = fminf(fmaxf(-128.0f - rintf(bmin * inv), -128.0f), 127.0f);
    if (tid == 0) g_sz[token] = make_float2(scale, zp);

#define QI(f) ((int)(fminf(fmaxf(rintf((f) * inv) + zp, -128.0f), 127.0f)))
    uint32_t p0, p1;
    {
        int q0 = QI(v0.x), q1 = QI(v0.y), q2 = QI(v0.z), q3 = QI(v0.w);
        p0 = (q0 & 0xFF) | ((q1 & 0xFF) << 8) | ((q2 & 0xFF) << 16) | ((q3 & 0xFF) << 24);
        q0 = QI(v1.x); q1 = QI(v1.y); q2 = QI(v1.z); q3 = QI(v1.w);
        p1 = (q0 & 0xFF) | ((q1 & 0xFF) << 8) | ((q2 & 0xFF) << 16) | ((q3 & 0xFF) << 24);
    }
#undef QI
    uint32_t* aw = (uint32_t*)(g_Aq + (size_t)token * DIN);
    aw[tid] = p0;
    aw[tid + 256] = p1;
}

// ---------------------------------------------------------------------------
// Kernel 2: weight repack int32 -> int8 + per-row colsum.
// ---------------------------------------------------------------------------
__global__ void wprep_kernel(const int4* __restrict__ w_int,
                             const float* __restrict__ ws,
                             const float* __restrict__ wz) {
    const int o = blockIdx.x;
    const int t = threadIdx.x;  // 256; covers k = 8t..8t+7
    const int4* wr = w_int + (size_t)o * (DIN / 4) + t * 2;
    int4 a = wr[0], b = wr[1];

    uint32_t p0 = (a.x & 0xFF) | ((a.y & 0xFF) << 8) | ((a.z & 0xFF) << 16) | ((a.w & 0xFF) << 24);
    uint32_t p1 = (b.x & 0xFF) | ((b.y & 0xFF) << 8) | ((b.z & 0xFF) << 16) | ((b.w & 0xFF) << 24);
    ((uint2*)(g_Wq + (size_t)o * DIN))[t] = make_uint2(p0, p1);

    int s8 = a.x + a.y + a.z + a.w + b.x + b.y + b.z + b.w;
    s8 += __shfl_xor_sync(0xffffffffu, s8, 1);
    s8 += __shfl_xor_sync(0xffffffffu, s8, 2);   // sum over group of 32

    __shared__ float part[64];
    if ((t & 3) == 0) {
        const int g = t >> 2;
        part[g] = ws[o * NG + g] * ((float)s8 - 32.0f * wz[o * NG + g]);
    }
    __syncthreads();
    if (t < 32) {
        float v = part[t] + part[t + 32];
#pragma unroll
        for (int off = 16; off > 0; off >>= 1)
            v += __shfl_xor_sync(0xffffffffu, v, off);
        if (t == 0) g_colsum[o] = v;
    }
}

// ---------------------------------------------------------------------------
// Kernel 3: int8 grouped GEMM, conversion-free.
// mma C-input = MAGIC so d = float-bits of (12582912 + S_g) exactly.
// Packed f32x2: t = d2 + (-B,-B);  acc2 = s01*t + acc2.
// out[m,n] = s_x[m]*( sum_g s_w[n,g]*S_g(m,n) - zp[m]*colsum[n] )
// ---------------------------------------------------------------------------
extern __shared__ char dsmem[];

__global__ void gemm_kernel(float* __restrict__ out, const float* __restrict__ ws) {
    const int tid  = threadIdx.x;      // 256
    const int lane = tid & 31;
    const int wid  = tid >> 5;
    const int warp_m = wid >> 2;       // 0..1  -> 64 rows
    const int warp_n = wid & 3;        // 0..3  -> 32 cols
    const int bn = blockIdx.x, bm = blockIdx.y;

    const int8_t* Aq = g_Aq + (size_t)(bm * BM) * DIN;
    const int8_t* Wq = g_Wq + (size_t)(bn * BN) * DIN;

    const uint32_t sb = (uint32_t)__cvta_generic_to_shared(dsmem);
    const uint32_t tiles = sb + SC_BYTES;
    float2* sws2 = (float2*)dsmem;     // [64 colpairs][SC_PITCH2] packed scales

    auto load_stage = [&](int s, int kt) {
        const uint32_t aB = tiles + s * STAGE_B;
        const uint32_t bB = aB + TILE_B;
        const int kb = kt * BKB;
#pragma unroll
        for (int j = 0; j < 2; j++) {
            const int c = tid + j * 256;
            const int r = c >> 2, off = (c & 3) * 16;
            cp_async16(aB + (uint32_t)(r * PITCHB + off), Aq + (size_t)r * DIN + kb + off);
            cp_async16(bB + (uint32_t)(r * PITCHB + off), Wq + (size_t)r * DIN + kb + off);
        }
        cp_commit();
    };

    load_stage(0, 0);
    load_stage(1, 1);

    // Pack w_scales for this CTA: sws2[cp][g] = (s[2cp][g], s[2cp+1][g])
#pragma unroll
    for (int i = 0; i < 16; i++) {
        const int idx = tid + i * 256;            // 4096 slots
        const int cp = idx >> 6, g = idx & 63;
        const float sa = ws[(size_t)(bn * BN + 2 * cp) * NG + g];
        const float sbv = ws[(size_t)(bn * BN + 2 * cp + 1) * NG + g];
        sws2[cp * SC_PITCH2 + g] = make_float2(sa, sbv);
    }

    unsigned long long acc2[4][4][2];
#pragma unroll
    for (int i = 0; i < 4; i++)
#pragma unroll
        for (int j = 0; j < 4; j++) { acc2[i][j][0] = 0ULL; acc2[i][j][1] = 0ULL; }

    // ldmatrix per-lane offsets (byte units, int8) — R7-proven
    const int a_row  = warp_m * 64 + (lane & 15);
    const int a_koff = (lane >> 4) * 16;
    const int b_row  = warp_n * 32 + (lane & 7) + ((lane >> 4) & 1) * 8;
    const int b_koff = ((lane >> 3) & 1) * 16;
    const int sc_cp  = warp_n * 16 + (lane & 3);   // colpair base for this lane

    int s_cur = 0, s_nxt = 2;
#pragma unroll 1
    for (int kt = 0; kt < NKT; kt++) {
        if (kt + 1 < NKT) cp_wait<1>(); else cp_wait<0>();
        __syncthreads();
        if (kt + 2 < NKT) load_stage(s_nxt, kt + 2);

        const uint32_t aBase = tiles + s_cur * STAGE_B;
        const uint32_t bBase = aBase + TILE_B;
        s_nxt = s_cur;
        s_cur = (s_cur == 2) ? 0 : s_cur + 1;

#pragma unroll
        for (int ks = 0; ks < 2; ks++) {          // one group (K=32) per step
            const int g = kt * 2 + ks;
            uint32_t af[4][4];
#pragma unroll
            for (int mt = 0; mt < 4; mt++) {
                uint32_t addr = aBase +
                    (uint32_t)((a_row + mt * 16) * PITCHB + ks * 32 + a_koff);
                asm volatile(
                    "ldmatrix.sync.aligned.m8n8.x4.shared.b16 {%0,%1,%2,%3}, [%4];"
                    : "=r"(af[mt][0]), "=r"(af[mt][1]), "=r"(af[mt][2]), "=r"(af[mt][3])
                    : "r"(addr));
            }
            uint32_t bf[4][2];
#pragma unroll
            for (int p = 0; p < 2; p++) {
                uint32_t addr = bBase +
                    (uint32_t)((b_row + p * 16) * PITCHB + ks * 32 + b_koff);
                uint32_t r0, r1, r2, r3;
                asm volatile(
                    "ldmatrix.sync.aligned.m8n8.x4.shared.b16 {%0,%1,%2,%3}, [%4];"
                    : "=r"(r0), "=r"(r1), "=r"(r2), "=r"(r3)
                    : "r"(addr));
                bf[2 * p][0] = r0; bf[2 * p][1] = r1;
                bf[2 * p + 1][0] = r2; bf[2 * p + 1][1] = r3;
            }
            // packed group scales: one LDS.64 per nt
            unsigned long long s01[4];
#pragma unroll
            for (int nt = 0; nt < 4; nt++) {
                const uint32_t saddr = sb + (uint32_t)((sc_cp + nt * 4) * SC_PITCH2 + g) * 8;
                asm volatile("ld.shared.b64 %0, [%1];" : "=l"(s01[nt]) : "r"(saddr));
            }
#pragma unroll
            for (int mt = 0; mt < 4; mt++)
#pragma unroll
                for (int nt = 0; nt < 4; nt++) {
                    int d0, d1, d2, d3;
                    asm volatile(
                        "mma.sync.aligned.m16n8k32.row.col.s32.s8.s8.s32 "
                        "{%0,%1,%2,%3}, {%4,%5,%6,%7}, {%8,%9}, {%10,%10,%10,%10};"
                        : "=r"(d0), "=r"(d1), "=r"(d2), "=r"(d3)
                        : "r"(af[mt][0]), "r"(af[mt][1]), "r"(af[mt][2]), "r"(af[mt][3]),
                          "r"(bf[nt][0]), "r"(bf[nt][1]), "r"(MAGICI));
                    unsigned long long p01, p23, t01, t23;
                    asm volatile("mov.b64 %0, {%1,%2};" : "=l"(p01) : "r"(d0), "r"(d1));
                    asm volatile("mov.b64 %0, {%1,%2};" : "=l"(p23) : "r"(d2), "r"(d3));
                    asm volatile("add.rn.f32x2 %0, %1, %2;" : "=l"(t01) : "l"(p01), "l"(NEGB2));
                    asm volatile("add.rn.f32x2 %0, %1, %2;" : "=l"(t23) : "l"(p23), "l"(NEGB2));
                    asm volatile("fma.rn.f32x2 %0, %1, %2, %0;"
                                 : "+l"(acc2[mt][nt][0]) : "l"(s01[nt]), "l"(t01));
                    asm volatile("fma.rn.f32x2 %0, %1, %2, %0;"
                                 : "+l"(acc2[mt][nt][1]) : "l"(s01[nt]), "l"(t23));
                }
        }
    }

    // Epilogue: out = s_x*(acc - zp*colsum)
    const int gm0 = bm * BM + warp_m * 64 + (lane >> 2);
    const int gn0 = bn * BN + warp_n * 32 + (lane & 3) * 2;
#pragma unroll
    for (int mt = 0; mt < 4; mt++) {
        const int r0 = gm0 + mt * 16;
        const float2 sz0 = g_sz[r0];
        const float2 sz1 = g_sz[r0 + 8];
#pragma unroll
        for (int nt = 0; nt < 4; nt++) {
            const int c = gn0 + nt * 8;
            const float2 cs = *(const float2*)&g_colsum[c];
            uint32_t a0, a1, a2, a3;
            asm volatile("mov.b64 {%0,%1}, %2;" : "=r"(a0), "=r"(a1) : "l"(acc2[mt][nt][0]));
            asm volatile("mov.b64 {%0,%1}, %2;" : "=r"(a2), "=r"(a3) : "l"(acc2[mt][nt][1]));
            float2 v0 = make_float2(sz0.x * (__uint_as_float(a0) - sz0.y * cs.x),
                                    sz0.x * (__uint_as_float(a1) - sz0.y * cs.y));
            float2 v1 = make_float2(sz1.x * (__uint_as_float(a2) - sz1.y * cs.x),
                                    sz1.x * (__uint_as_float(a3) - sz1.y * cs.y));
            *(float2*)&out[(size_t)r0 * DOUT + c] = v0;
            *(float2*)&out[(size_t)(r0 + 8) * DOUT + c] = v1;
        }
    }
}

// ---------------------------------------------------------------------------
extern "C" void kernel_launch(void* const* d_in, const int* in_sizes, int n_in,
                              void* d_out, int out_size) {
    (void)in_sizes; (void)n_in; (void)out_size;
    const float* x      = (const float*)d_in[0];
    const int*   w_int  = (const int*)d_in[1];
    const float* w_sc   = (const float*)d_in[2];
    const float* w_zp   = (const float*)d_in[3];
    float* out = (float*)d_out;

    cudaFuncSetAttribute(gemm_kernel, cudaFuncAttributeMaxDynamicSharedMemorySize, SMEM_TOTAL);

    quant_x_kernel<<<MTOT, 256>>>((const float4*)x);
    wprep_kernel<<<DOUT, 256>>>((const int4*)w_int, w_sc, w_zp);
    gemm_kernel<<<dim3(DOUT / BN, MTOT / BM), 256, SMEM_TOTAL>>>(out, w_sc);
}

// round 10
// speedup vs baseline: 2.4827x; 2.4368x over previous
#include <cuda_runtime.h>
#include <cuda_fp16.h>
#include <cstdint>

#define BATCH 4
#define SEQ   2048
#define DIN   2048
#define DOUT  2048
#define MTOT  (BATCH * SEQ)   // 8192 tokens
#define GROUP 32
#define NGROUP (DIN / GROUP)  // 64

// GEMM tiling (R5-proven config, 4-stage pipeline)
#define BM 128
#define BN 128
#define BK 32                 // halves per K-chunk
#define STAGES 4
#define NKT (DIN / BK)        // 64
#define PITCH 40              // halves per smem row (80B, conflict-free ldmatrix)
#define A_BYTES (BM * PITCH * 2)      // 10240
#define B_BYTES (BN * PITCH * 2)      // 10240
#define STAGE_B (A_BYTES + B_BYTES)   // 20480
#define SMEM_TOTAL (STAGES * STAGE_B) // 81920

// Scratch (allocation-free rule: __device__ globals)
__device__ __half g_A[(size_t)MTOT * DIN];   // exact integer (q - zp) per token
__device__ __half g_W[(size_t)DOUT * DIN];   // dequantized weights
__device__ float  g_sx[MTOT];                // per-token activation scale

// ---------------------------------------------------------------------------
__device__ __forceinline__ void cp_async16(uint32_t saddr, const void* gaddr) {
    asm volatile("cp.async.cg.shared.global [%0], [%1], 16;\n" :: "r"(saddr), "l"(gaddr));
}
__device__ __forceinline__ void cp_commit() { asm volatile("cp.async.commit_group;\n" ::: "memory"); }
template <int N>
__device__ __forceinline__ void cp_wait() { asm volatile("cp.async.wait_group %0;\n" :: "n"(N) : "memory"); }

// ---------------------------------------------------------------------------
// Kernel 1: per-token asymmetric int8 fake-quant of x (float4 vectorized).
// Stores (q - zp) (integer in [-255,255], EXACT in fp16) and scale separately.
// ---------------------------------------------------------------------------
__global__ void quant_x_kernel(const float4* __restrict__ x) {
    const int token = blockIdx.x;
    const float4* xr = x + (size_t)token * (DIN / 4);
    const int tid = threadIdx.x;  // 256 threads

    float4 v0 = xr[tid];
    float4 v1 = xr[tid + 256];
    float vmin = fminf(fminf(fminf(v0.x, v0.y), fminf(v0.z, v0.w)),
                       fminf(fminf(v1.x, v1.y), fminf(v1.z, v1.w)));
    float vmax = fmaxf(fmaxf(fmaxf(v0.x, v0.y), fmaxf(v0.z, v0.w)),
                       fmaxf(fmaxf(v1.x, v1.y), fmaxf(v1.z, v1.w)));
    vmin = fminf(vmin, 0.0f);
    vmax = fmaxf(vmax, 0.0f);
#pragma unroll
    for (int off = 16; off > 0; off >>= 1) {
        vmin = fminf(vmin, __shfl_xor_sync(0xffffffffu, vmin, off));
        vmax = fmaxf(vmax, __shfl_xor_sync(0xffffffffu, vmax, off));
    }
    __shared__ float smin[8], smax[8];
    if ((tid & 31) == 0) { smin[tid >> 5] = vmin; smax[tid >> 5] = vmax; }
    __syncthreads();
    float bmin = smin[0], bmax = smax[0];
#pragma unroll
    for (int i = 1; i < 8; i++) { bmin = fminf(bmin, smin[i]); bmax = fmaxf(bmax, smax[i]); }

    float scale = (bmax - bmin) / 255.0f;
    scale = fmaxf(scale, 1.1920928955078125e-07f);  // jnp.finfo(f32).eps
    float inv = 1.0f / scale;
    float zp = fminf(fmaxf(-128.0f - rintf(bmin * inv), -128.0f), 127.0f);
    if (tid == 0) g_sx[token] = scale;

    __half2* ar = (__half2*)(g_A + (size_t)token * DIN);
#define QV(f) (fminf(fmaxf(rintf((f) * inv) + zp, -128.0f), 127.0f) - zp)
    ar[2 * tid + 0]         = __floats2half2_rn(QV(v0.x), QV(v0.y));
    ar[2 * tid + 1]         = __floats2half2_rn(QV(v0.z), QV(v0.w));
    ar[2 * (tid + 256) + 0] = __floats2half2_rn(QV(v1.x), QV(v1.y));
    ar[2 * (tid + 256) + 1] = __floats2half2_rn(QV(v1.z), QV(v1.w));
#undef QV
}

// ---------------------------------------------------------------------------
// Kernel 2: int4 grouped weight dequant -> fp16
// ---------------------------------------------------------------------------
__global__ void wdq_kernel(const int4* __restrict__ w_int,
                           const float* __restrict__ ws,
                           const float* __restrict__ wz) {
    const int idx = blockIdx.x * 256 + threadIdx.x;  // over DOUT*DIN/4
    int4 w = w_int[idx];
    const int k4 = idx & (DIN / 4 - 1);
    const int o  = idx / (DIN / 4);
    const int g  = (k4 * 4) / GROUP;
    const float s = ws[o * NGROUP + g];
    const float z = wz[o * NGROUP + g];
    __half2 lo = __floats2half2_rn(((float)w.x - z) * s, ((float)w.y - z) * s);
    __half2 hi = __floats2half2_rn(((float)w.z - z) * s, ((float)w.w - z) * s);
    __half2* dst = (__half2*)g_W + (size_t)idx * 2;
    dst[0] = lo;
    dst[1] = hi;
}

// ---------------------------------------------------------------------------
// Kernel 3: GEMM  out[m,n] = s_x[m] * sum_k A[m,k] * W[n,k]
// 128x128 CTA tile, 8 warps (2x4), warp tile 64x32, 4-stage cp.async
// (wait_group 2, load-after-sync, empty-commit tail), ldmatrix + mma m16n8k16.
// ---------------------------------------------------------------------------
extern __shared__ char dsmem[];

__global__ void gemm_kernel(float* __restrict__ out) {
    const int tid  = threadIdx.x;      // 256
    const int lane = tid & 31;
    const int wid  = tid >> 5;
    const int warp_m = wid >> 2;       // 0..1  -> 64 rows
    const int warp_n = wid & 3;        // 0..3  -> 32 cols
    const int bn = blockIdx.x, bm = blockIdx.y;

    const __half* Ag = g_A + (size_t)(bm * BM) * DIN;
    const __half* Wg = g_W + (size_t)(bn * BN) * DIN;

    const uint32_t sb = (uint32_t)__cvta_generic_to_shared(dsmem);

    // cp.async chunk mapping: 512 chunks (A) + 512 (B), 2+2 per thread
    const int arow = tid >> 2;          // 0..63
    const int cc   = (tid & 3) * 8;     // chunk col in halves

    auto load_stage = [&](int s, int kt) {
        const uint32_t aBase = sb + s * STAGE_B;
        const uint32_t bBase = aBase + A_BYTES;
        const int kh = kt * BK;
#pragma unroll
        for (int j = 0; j < 2; j++) {
            const int r = arow + j * 64;
            cp_async16(aBase + (uint32_t)(r * PITCH + cc) * 2,
                       Ag + (size_t)r * DIN + kh + cc);
            cp_async16(bBase + (uint32_t)(r * PITCH + cc) * 2,
                       Wg + (size_t)r * DIN + kh + cc);
        }
        cp_commit();
    };

    float acc[4][4][4];
#pragma unroll
    for (int i = 0; i < 4; i++)
#pragma unroll
        for (int j = 0; j < 4; j++)
#pragma unroll
            for (int r = 0; r < 4; r++) acc[i][j][r] = 0.0f;

    // ldmatrix per-lane offsets (within tile)
    const int a_row = warp_m * 64 + (lane & 15);
    const int a_col = (lane >> 4) * 8;
    const int b_row = warp_n * 32 + (lane & 7) + ((lane >> 4) & 1) * 8;
    const int b_col = ((lane >> 3) & 1) * 8;

    load_stage(0, 0);
    load_stage(1, 1);
    load_stage(2, 2);

#pragma unroll 1
    for (int kt = 0; kt < NKT; kt++) {
        cp_wait<2>();          // oldest pending group (stage kt) complete
        __syncthreads();
        if (kt + 3 < NKT) load_stage((kt + 3) & (STAGES - 1), kt + 3);
        else cp_commit();      // empty group keeps wait<2> arithmetic exact

        const uint32_t aBase = sb + (kt & (STAGES - 1)) * STAGE_B;
        const uint32_t bBase = aBase + A_BYTES;

#pragma unroll
        for (int ks = 0; ks < 2; ks++) {
            uint32_t af[4][4];
#pragma unroll
            for (int mt = 0; mt < 4; mt++) {
                uint32_t addr = aBase +
                    (uint32_t)(((a_row + mt * 16) * PITCH) + ks * 16 + a_col) * 2;
                asm volatile(
                    "ldmatrix.sync.aligned.m8n8.x4.shared.b16 {%0,%1,%2,%3}, [%4];"
                    : "=r"(af[mt][0]), "=r"(af[mt][1]), "=r"(af[mt][2]), "=r"(af[mt][3])
                    : "r"(addr));
            }
            uint32_t bf[4][2];
#pragma unroll
            for (int p = 0; p < 2; p++) {
                uint32_t addr = bBase +
                    (uint32_t)(((b_row + p * 16) * PITCH) + ks * 16 + b_col) * 2;
                uint32_t r0, r1, r2, r3;
                asm volatile(
                    "ldmatrix.sync.aligned.m8n8.x4.shared.b16 {%0,%1,%2,%3}, [%4];"
                    : "=r"(r0), "=r"(r1), "=r"(r2), "=r"(r3)
                    : "r"(addr));
                bf[2 * p][0] = r0; bf[2 * p][1] = r1;
                bf[2 * p + 1][0] = r2; bf[2 * p + 1][1] = r3;
            }
#pragma unroll
            for (int mt = 0; mt < 4; mt++)
#pragma unroll
                for (int nt = 0; nt < 4; nt++)
                    asm volatile(
                        "mma.sync.aligned.m16n8k16.row.col.f32.f16.f16.f32 "
                        "{%0,%1,%2,%3}, {%4,%5,%6,%7}, {%8,%9}, {%0,%1,%2,%3};"
                        : "+f"(acc[mt][nt][0]), "+f"(acc[mt][nt][1]),
                          "+f"(acc[mt][nt][2]), "+f"(acc[mt][nt][3])
                        : "r"(af[mt][0]), "r"(af[mt][1]), "r"(af[mt][2]), "r"(af[mt][3]),
                          "r"(bf[nt][0]), "r"(bf[nt][1]));
        }
    }

    // Epilogue: scale rows by s_x and store fp32
    const int gm0 = bm * BM + warp_m * 64 + (lane >> 2);
    const int gn0 = bn * BN + warp_n * 32 + (lane & 3) * 2;
#pragma unroll
    for (int mt = 0; mt < 4; mt++) {
        const int r0 = gm0 + mt * 16;
        const float s0 = g_sx[r0];
        const float s1 = g_sx[r0 + 8];
#pragma unroll
        for (int nt = 0; nt < 4; nt++) {
            const int c = gn0 + nt * 8;
            float2 v0 = make_float2(acc[mt][nt][0] * s0, acc[mt][nt][1] * s0);
            float2 v1 = make_float2(acc[mt][nt][2] * s1, acc[mt][nt][3] * s1);
            *(float2*)&out[(size_t)r0 * DOUT + c] = v0;
            *(float2*)&out[(size_t)(r0 + 8) * DOUT + c] = v1;
        }
    }
}

// ---------------------------------------------------------------------------
extern "C" void kernel_launch(void* const* d_in, const int* in_sizes, int n_in,
                              void* d_out, int out_size) {
    (void)in_sizes; (void)n_in; (void)out_size;
    const float* x      = (const float*)d_in[0];
    const int*   w_int  = (const int*)d_in[1];
    const float* w_sc   = (const float*)d_in[2];
    const float* w_zp   = (const float*)d_in[3];
    float* out = (float*)d_out;

    cudaFuncSetAttribute(gemm_kernel, cudaFuncAttributeMaxDynamicSharedMemorySize, SMEM_TOTAL);

    quant_x_kernel<<<MTOT, 256>>>((const float4*)x);
    wdq_kernel<<<(DOUT * DIN / 4) / 256, 256>>>((const int4*)w_int, w_sc, w_zp);
    gemm_kernel<<<dim3(DOUT / BN, MTOT / BM), 256, SMEM_TOTAL>>>(out);
}

// round 11
// speedup vs baseline: 2.4962x; 1.0054x over previous
#include <cuda_runtime.h>
#include <cuda_fp16.h>
#include <cstdint>

#define BATCH 4
#define SEQ   2048
#define DIN   2048
#define DOUT  2048
#define MTOT  (BATCH * SEQ)   // 8192 tokens
#define GROUP 32
#define NGROUP (DIN / GROUP)  // 64

// GEMM tiling (R9-proven config: 4-stage, wait_group 2)
#define BM 128
#define BN 128
#define BK 32                 // halves per K-chunk
#define STAGES 4
#define NKT (DIN / BK)        // 64
#define PITCH 40              // halves per smem row (80B, conflict-free ldmatrix)
#define A_BYTES (BM * PITCH * 2)      // 10240
#define B_BYTES (BN * PITCH * 2)      // 10240
#define STAGE_B (A_BYTES + B_BYTES)   // 20480
#define SMEM_TOTAL (STAGES * STAGE_B) // 81920

// prep kernel partition
#define QBLOCKS (MTOT / 8)            // 1024 blocks x 8 warps = 1 token/warp
#define WBLOCKS (DOUT * DIN / 4 / 256) // 4096

// Scratch (allocation-free rule: __device__ globals)
__device__ __half g_A[(size_t)MTOT * DIN];   // exact integer (q - zp) per token
__device__ __half g_W[(size_t)DOUT * DIN];   // dequantized weights
__device__ float  g_sx[MTOT];                // per-token activation scale

// ---------------------------------------------------------------------------
__device__ __forceinline__ void cp_async16(uint32_t saddr, const void* gaddr) {
    asm volatile("cp.async.cg.shared.global [%0], [%1], 16;\n" :: "r"(saddr), "l"(gaddr));
}
__device__ __forceinline__ void cp_commit() { asm volatile("cp.async.commit_group;\n" ::: "memory"); }
template <int N>
__device__ __forceinline__ void cp_wait() { asm volatile("cp.async.wait_group %0;\n" :: "n"(N) : "memory"); }

// ---------------------------------------------------------------------------
// Kernel 1 (fused prep):
//  blocks [0, QBLOCKS): per-token asymmetric int8 fake-quant of x.
//    One token per WARP — no smem, no barriers, pure shuffle reduction.
//    Stores (q - zp) (integer in [-255,255], EXACT in fp16) + scale.
//  blocks [QBLOCKS, QBLOCKS+WBLOCKS): int4 grouped weight dequant -> fp16.
// ---------------------------------------------------------------------------
__global__ void prep_kernel(const float4* __restrict__ x,
                            const int4* __restrict__ w_int,
                            const float* __restrict__ ws,
                            const float* __restrict__ wz) {
    const int bid = blockIdx.x;
    if (bid < QBLOCKS) {
        // ---- quant: warp-per-token ----
        const int lane  = threadIdx.x & 31;
        const int token = bid * 8 + (threadIdx.x >> 5);
        const float4* xr = x + (size_t)token * (DIN / 4);

        float4 v[16];
        float vmin = 0.0f, vmax = 0.0f;   // reference clamps min<=0, max>=0
#pragma unroll
        for (int i = 0; i < 16; i++) {
            v[i] = xr[lane + 32 * i];
            vmin = fminf(vmin, fminf(fminf(v[i].x, v[i].y), fminf(v[i].z, v[i].w)));
            vmax = fmaxf(vmax, fmaxf(fmaxf(v[i].x, v[i].y), fmaxf(v[i].z, v[i].w)));
        }
#pragma unroll
        for (int off = 16; off > 0; off >>= 1) {
            vmin = fminf(vmin, __shfl_xor_sync(0xffffffffu, vmin, off));
            vmax = fmaxf(vmax, __shfl_xor_sync(0xffffffffu, vmax, off));
        }

        float scale = (vmax - vmin) / 255.0f;
        scale = fmaxf(scale, 1.1920928955078125e-07f);  // jnp.finfo(f32).eps
        const float inv = 1.0f / scale;
        const float zp = fminf(fmaxf(-128.0f - rintf(vmin * inv), -128.0f), 127.0f);
        if (lane == 0) g_sx[token] = scale;

        uint2* ar = (uint2*)(g_A + (size_t)token * DIN);  // 2 half2 per float4
#define QV(f) (fminf(fmaxf(rintf((f) * inv) + zp, -128.0f), 127.0f) - zp)
#pragma unroll
        for (int i = 0; i < 16; i++) {
            __half2 h0 = __floats2half2_rn(QV(v[i].x), QV(v[i].y));
            __half2 h1 = __floats2half2_rn(QV(v[i].z), QV(v[i].w));
            uint2 p;
            p.x = *(const uint32_t*)&h0;
            p.y = *(const uint32_t*)&h1;
            ar[lane + 32 * i] = p;
        }
#undef QV
    } else {
        // ---- weight dequant ----
        const int idx = (bid - QBLOCKS) * 256 + threadIdx.x;  // over DOUT*DIN/4
        int4 w = w_int[idx];
        const int k4 = idx & (DIN / 4 - 1);
        const int o  = idx / (DIN / 4);
        const int g  = (k4 * 4) / GROUP;
        const float s = ws[o * NGROUP + g];
        const float z = wz[o * NGROUP + g];
        __half2 lo = __floats2half2_rn(((float)w.x - z) * s, ((float)w.y - z) * s);
        __half2 hi = __floats2half2_rn(((float)w.z - z) * s, ((float)w.w - z) * s);
        __half2* dst = (__half2*)g_W + (size_t)idx * 2;
        dst[0] = lo;
        dst[1] = hi;
    }
}

// ---------------------------------------------------------------------------
// Kernel 2: GEMM  out[m,n] = s_x[m] * sum_k A[m,k] * W[n,k]
// 128x128 CTA tile, 8 warps (2x4), warp tile 64x32, 4-stage cp.async
// (wait_group 2, load-after-sync, empty-commit tail), ldmatrix + mma m16n8k16.
// BYTE-IDENTICAL to R9 (best: 243.7us).
// ---------------------------------------------------------------------------
extern __shared__ char dsmem[];

__global__ void gemm_kernel(float* __restrict__ out) {
    const int tid  = threadIdx.x;      // 256
    const int lane = tid & 31;
    const int wid  = tid >> 5;
    const int warp_m = wid >> 2;       // 0..1  -> 64 rows
    const int warp_n = wid & 3;        // 0..3  -> 32 cols
    const int bn = blockIdx.x, bm = blockIdx.y;

    const __half* Ag = g_A + (size_t)(bm * BM) * DIN;
    const __half* Wg = g_W + (size_t)(bn * BN) * DIN;

    const uint32_t sb = (uint32_t)__cvta_generic_to_shared(dsmem);

    // cp.async chunk mapping: 512 chunks (A) + 512 (B), 2+2 per thread
    const int arow = tid >> 2;          // 0..63
    const int cc   = (tid & 3) * 8;     // chunk col in halves

    auto load_stage = [&](int s, int kt) {
        const uint32_t aBase = sb + s * STAGE_B;
        const uint32_t bBase = aBase + A_BYTES;
        const int kh = kt * BK;
#pragma unroll
        for (int j = 0; j < 2; j++) {
            const int r = arow + j * 64;
            cp_async16(aBase + (uint32_t)(r * PITCH + cc) * 2,
                       Ag + (size_t)r * DIN + kh + cc);
            cp_async16(bBase + (uint32_t)(r * PITCH + cc) * 2,
                       Wg + (size_t)r * DIN + kh + cc);
        }
        cp_commit();
    };

    float acc[4][4][4];
#pragma unroll
    for (int i = 0; i < 4; i++)
#pragma unroll
        for (int j = 0; j < 4; j++)
#pragma unroll
            for (int r = 0; r < 4; r++) acc[i][j][r] = 0.0f;

    // ldmatrix per-lane offsets (within tile)
    const int a_row = warp_m * 64 + (lane & 15);
    const int a_col = (lane >> 4) * 8;
    const int b_row = warp_n * 32 + (lane & 7) + ((lane >> 4) & 1) * 8;
    const int b_col = ((lane >> 3) & 1) * 8;

    load_stage(0, 0);
    load_stage(1, 1);
    load_stage(2, 2);

#pragma unroll 1
    for (int kt = 0; kt < NKT; kt++) {
        cp_wait<2>();          // oldest pending group (stage kt) complete
        __syncthreads();
        if (kt + 3 < NKT) load_stage((kt + 3) & (STAGES - 1), kt + 3);
        else cp_commit();      // empty group keeps wait<2> arithmetic exact

        const uint32_t aBase = sb + (kt & (STAGES - 1)) * STAGE_B;
        const uint32_t bBase = aBase + A_BYTES;

#pragma unroll
        for (int ks = 0; ks < 2; ks++) {
            uint32_t af[4][4];
#pragma unroll
            for (int mt = 0; mt < 4; mt++) {
                uint32_t addr = aBase +
                    (uint32_t)(((a_row + mt * 16) * PITCH) + ks * 16 + a_col) * 2;
                asm volatile(
                    "ldmatrix.sync.aligned.m8n8.x4.shared.b16 {%0,%1,%2,%3}, [%4];"
                    : "=r"(af[mt][0]), "=r"(af[mt][1]), "=r"(af[mt][2]), "=r"(af[mt][3])
                    : "r"(addr));
            }
            uint32_t bf[4][2];
#pragma unroll
            for (int p = 0; p < 2; p++) {
                uint32_t addr = bBase +
                    (uint32_t)(((b_row + p * 16) * PITCH) + ks * 16 + b_col) * 2;
                uint32_t r0, r1, r2, r3;
                asm volatile(
                    "ldmatrix.sync.aligned.m8n8.x4.shared.b16 {%0,%1,%2,%3}, [%4];"
                    : "=r"(r0), "=r"(r1), "=r"(r2), "=r"(r3)
                    : "r"(addr));
                bf[2 * p][0] = r0; bf[2 * p][1] = r1;
                bf[2 * p + 1][0] = r2; bf[2 * p + 1][1] = r3;
            }
#pragma unroll
            for (int mt = 0; mt < 4; mt++)
#pragma unroll
                for (int nt = 0; nt < 4; nt++)
                    asm volatile(
                        "mma.sync.aligned.m16n8k16.row.col.f32.f16.f16.f32 "
                        "{%0,%1,%2,%3}, {%4,%5,%6,%7}, {%8,%9}, {%0,%1,%2,%3};"
                        : "+f"(acc[mt][nt][0]), "+f"(acc[mt][nt][1]),
                          "+f"(acc[mt][nt][2]), "+f"(acc[mt][nt][3])
                        : "r"(af[mt][0]), "r"(af[mt][1]), "r"(af[mt][2]), "r"(af[mt][3]),
                          "r"(bf[nt][0]), "r"(bf[nt][1]));
        }
    }

    // Epilogue: scale rows by s_x and store fp32
    const int gm0 = bm * BM + warp_m * 64 + (lane >> 2);
    const int gn0 = bn * BN + warp_n * 32 + (lane & 3) * 2;
#pragma unroll
    for (int mt = 0; mt < 4; mt++) {
        const int r0 = gm0 + mt * 16;
        const float s0 = g_sx[r0];
        const float s1 = g_sx[r0 + 8];
#pragma unroll
        for (int nt = 0; nt < 4; nt++) {
            const int c = gn0 + nt * 8;
            float2 v0 = make_float2(acc[mt][nt][0] * s0, acc[mt][nt][1] * s0);
            float2 v1 = make_float2(acc[mt][nt][2] * s1, acc[mt][nt][3] * s1);
            *(float2*)&out[(size_t)r0 * DOUT + c] = v0;
            *(float2*)&out[(size_t)(r0 + 8) * DOUT + c] = v1;
        }
    }
}

// ---------------------------------------------------------------------------
extern "C" void kernel_launch(void* const* d_in, const int* in_sizes, int n_in,
                              void* d_out, int out_size) {
    (void)in_sizes; (void)n_in; (void)out_size;
    const float* x      = (const float*)d_in[0];
    const int*   w_int  = (const int*)d_in[1];
    const float* w_sc   = (const float*)d_in[2];
    const float* w_zp   = (const float*)d_in[3];
    float* out = (float*)d_out;

    cudaFuncSetAttribute(gemm_kernel, cudaFuncAttributeMaxDynamicSharedMemorySize, SMEM_TOTAL);

    prep_kernel<<<QBLOCKS + WBLOCKS, 256>>>((const float4*)x, (const int4*)w_int, w_sc, w_zp);
    gemm_kernel<<<dim3(DOUT / BN, MTOT / BM), 256, SMEM_TOTAL>>>(out);
}

// round 12
// speedup vs baseline: 2.7782x; 1.1130x over previous
#include <cuda_runtime.h>
#include <cuda_fp16.h>
#include <cstdint>

#define BATCH 4
#define SEQ   2048
#define DIN   2048
#define DOUT  2048
#define MTOT  (BATCH * SEQ)   // 8192 tokens
#define GROUP 32
#define NGROUP (DIN / GROUP)  // 64

// GEMM tiling: 128x128 CTA tile, BK=64 halves (one 128B row), 3 stages
#define BM 128
#define BN 128
#define BK 64                 // halves per K-chunk
#define STAGES 3
#define NKT (DIN / BK)        // 32
#define PITCH 72              // halves per smem row (144B, conflict-free ldmatrix)
#define ROWB (PITCH * 2)      // 144 bytes
#define A_BYTES (BM * ROWB)           // 18432
#define STAGE_B (2 * A_BYTES)         // 36864
#define SMEM_TOTAL (STAGES * STAGE_B) // 110592

// prep kernel partition
#define QBLOCKS (MTOT / 8)             // 1024 blocks x 8 warps = 1 token/warp
#define WBLOCKS (DOUT * DIN / 4 / 256) // 4096

// Scratch (allocation-free rule: __device__ globals)
__device__ __half g_A[(size_t)MTOT * DIN];   // exact integer (q - zp) per token
__device__ __half g_W[(size_t)DOUT * DIN];   // dequantized weights
__device__ float  g_sx[MTOT];                // per-token activation scale

// ---------------------------------------------------------------------------
__device__ __forceinline__ void cp_async16(uint32_t saddr, const void* gaddr) {
    asm volatile("cp.async.cg.shared.global [%0], [%1], 16;\n" :: "r"(saddr), "l"(gaddr));
}
__device__ __forceinline__ void cp_commit() { asm volatile("cp.async.commit_group;\n" ::: "memory"); }
template <int N>
__device__ __forceinline__ void cp_wait() { asm volatile("cp.async.wait_group %0;\n" :: "n"(N) : "memory"); }

// ---------------------------------------------------------------------------
// Kernel 1 (fused prep): R10-proven.
//  blocks [0, QBLOCKS): warp-per-token int8 fake-quant of x (shuffle-only).
//  blocks [QBLOCKS, ...): int4 grouped weight dequant -> fp16.
// ---------------------------------------------------------------------------
__global__ void prep_kernel(const float4* __restrict__ x,
                            const int4* __restrict__ w_int,
                            const float* __restrict__ ws,
                            const float* __restrict__ wz) {
    const int bid = blockIdx.x;
    if (bid < QBLOCKS) {
        const int lane  = threadIdx.x & 31;
        const int token = bid * 8 + (threadIdx.x >> 5);
        const float4* xr = x + (size_t)token * (DIN / 4);

        float4 v[16];
        float vmin = 0.0f, vmax = 0.0f;   // reference clamps min<=0, max>=0
#pragma unroll
        for (int i = 0; i < 16; i++) {
            v[i] = xr[lane + 32 * i];
            vmin = fminf(vmin, fminf(fminf(v[i].x, v[i].y), fminf(v[i].z, v[i].w)));
            vmax = fmaxf(vmax, fmaxf(fmaxf(v[i].x, v[i].y), fmaxf(v[i].z, v[i].w)));
        }
#pragma unroll
        for (int off = 16; off > 0; off >>= 1) {
            vmin = fminf(vmin, __shfl_xor_sync(0xffffffffu, vmin, off));
            vmax = fmaxf(vmax, __shfl_xor_sync(0xffffffffu, vmax, off));
        }

        float scale = (vmax - vmin) / 255.0f;
        scale = fmaxf(scale, 1.1920928955078125e-07f);  // jnp.finfo(f32).eps
        const float inv = 1.0f / scale;
        const float zp = fminf(fmaxf(-128.0f - rintf(vmin * inv), -128.0f), 127.0f);
        if (lane == 0) g_sx[token] = scale;

        uint2* ar = (uint2*)(g_A + (size_t)token * DIN);
#define QV(f) (fminf(fmaxf(rintf((f) * inv) + zp, -128.0f), 127.0f) - zp)
#pragma unroll
        for (int i = 0; i < 16; i++) {
            __half2 h0 = __floats2half2_rn(QV(v[i].x), QV(v[i].y));
            __half2 h1 = __floats2half2_rn(QV(v[i].z), QV(v[i].w));
            uint2 p;
            p.x = *(const uint32_t*)&h0;
            p.y = *(const uint32_t*)&h1;
            ar[lane + 32 * i] = p;
        }
#undef QV
    } else {
        const int idx = (bid - QBLOCKS) * 256 + threadIdx.x;  // over DOUT*DIN/4
        int4 w = w_int[idx];
        const int k4 = idx & (DIN / 4 - 1);
        const int o  = idx / (DIN / 4);
        const int g  = (k4 * 4) / GROUP;
        const float s = ws[o * NGROUP + g];
        const float z = wz[o * NGROUP + g];
        __half2 lo = __floats2half2_rn(((float)w.x - z) * s, ((float)w.y - z) * s);
        __half2 hi = __floats2half2_rn(((float)w.z - z) * s, ((float)w.w - z) * s);
        __half2* dst = (__half2*)g_W + (size_t)idx * 2;
        dst[0] = lo;
        dst[1] = hi;
    }
}

// ---------------------------------------------------------------------------
// Kernel 2: GEMM  out[m,n] = s_x[m] * sum_k A[m,k] * W[n,k]
// 128x128 CTA tile, 8 warps (2x4), warp tile 64x32, BK=64 (4 ks sub-steps),
// 3-stage cp.async wait_group 1, ldmatrix + mma m16n8k16.
// ---------------------------------------------------------------------------
extern __shared__ char dsmem[];

__global__ void gemm_kernel(float* __restrict__ out) {
    const int tid  = threadIdx.x;      // 256
    const int lane = tid & 31;
    const int wid  = tid >> 5;
    const int warp_m = wid >> 2;       // 0..1  -> 64 rows
    const int warp_n = wid & 3;        // 0..3  -> 32 cols
    const int bn = blockIdx.x, bm = blockIdx.y;

    const __half* Ag = g_A + (size_t)(bm * BM) * DIN;
    const __half* Wg = g_W + (size_t)(bn * BN) * DIN;

    const uint32_t sb = (uint32_t)__cvta_generic_to_shared(dsmem);

    // cp.async chunk mapping: 1024 chunks per operand, 4+4 per thread
    const int crow = tid >> 3;           // base row 0..31 band
    const int ccb  = (tid & 7) * 16;     // chunk col in bytes

    auto load_stage = [&](int s, int kt) {
        const uint32_t aBase = sb + s * STAGE_B;
        const uint32_t bBase = aBase + A_BYTES;
        const int kh = kt * BK;          // half offset in K
        const int ch = ccb / 2;          // halves
#pragma unroll
        for (int j = 0; j < 4; j++) {
            const int r = crow + j * 32;
            cp_async16(aBase + (uint32_t)(r * ROWB + ccb), Ag + (size_t)r * DIN + kh + ch);
            cp_async16(bBase + (uint32_t)(r * ROWB + ccb), Wg + (size_t)r * DIN + kh + ch);
        }
        cp_commit();
    };

    float acc[4][4][4];
#pragma unroll
    for (int i = 0; i < 4; i++)
#pragma unroll
        for (int j = 0; j < 4; j++)
#pragma unroll
            for (int r = 0; r < 4; r++) acc[i][j][r] = 0.0f;

    // ldmatrix per-lane offsets (rows; byte col offsets)
    const int a_row  = warp_m * 64 + (lane & 15);
    const int a_colb = (lane >> 4) * 16;
    const int b_row  = warp_n * 32 + (lane & 7) + ((lane >> 4) & 1) * 8;
    const int b_colb = ((lane >> 3) & 1) * 16;

    load_stage(0, 0);
    load_stage(1, 1);

    int s_cur = 0, s_nxt = 2;   // rotating stage indices
#pragma unroll 1
    for (int kt = 0; kt < NKT; kt++) {
        if (kt + 1 < NKT) cp_wait<1>(); else cp_wait<0>();
        __syncthreads();
        if (kt + 2 < NKT) load_stage(s_nxt, kt + 2);

        const uint32_t aBase = sb + s_cur * STAGE_B;
        const uint32_t bBase = aBase + A_BYTES;
        s_nxt = s_cur;
        s_cur = (s_cur == 2) ? 0 : s_cur + 1;

#pragma unroll
        for (int ks = 0; ks < 4; ks++) {
            uint32_t af[4][4];
#pragma unroll
            for (int mt = 0; mt < 4; mt++) {
                uint32_t addr = aBase +
                    (uint32_t)((a_row + mt * 16) * ROWB + ks * 32 + a_colb);
                asm volatile(
                    "ldmatrix.sync.aligned.m8n8.x4.shared.b16 {%0,%1,%2,%3}, [%4];"
                    : "=r"(af[mt][0]), "=r"(af[mt][1]), "=r"(af[mt][2]), "=r"(af[mt][3])
                    : "r"(addr));
            }
            uint32_t bf[4][2];
#pragma unroll
            for (int p = 0; p < 2; p++) {
                uint32_t addr = bBase +
                    (uint32_t)((b_row + p * 16) * ROWB + ks * 32 + b_colb);
                uint32_t r0, r1, r2, r3;
                asm volatile(
                    "ldmatrix.sync.aligned.m8n8.x4.shared.b16 {%0,%1,%2,%3}, [%4];"
                    : "=r"(r0), "=r"(r1), "=r"(r2), "=r"(r3)
                    : "r"(addr));
                bf[2 * p][0] = r0; bf[2 * p][1] = r1;
                bf[2 * p + 1][0] = r2; bf[2 * p + 1][1] = r3;
            }
#pragma unroll
            for (int mt = 0; mt < 4; mt++)
#pragma unroll
                for (int nt = 0; nt < 4; nt++)
                    asm volatile(
                        "mma.sync.aligned.m16n8k16.row.col.f32.f16.f16.f32 "
                        "{%0,%1,%2,%3}, {%4,%5,%6,%7}, {%8,%9}, {%0,%1,%2,%3};"
                        : "+f"(acc[mt][nt][0]), "+f"(acc[mt][nt][1]),
                          "+f"(acc[mt][nt][2]), "+f"(acc[mt][nt][3])
                        : "r"(af[mt][0]), "r"(af[mt][1]), "r"(af[mt][2]), "r"(af[mt][3]),
                          "r"(bf[nt][0]), "r"(bf[nt][1]));
        }
    }

    // Epilogue: scale rows by s_x and store fp32
    const int gm0 = bm * BM + warp_m * 64 + (lane >> 2);
    const int gn0 = bn * BN + warp_n * 32 + (lane & 3) * 2;
#pragma unroll
    for (int mt = 0; mt < 4; mt++) {
        const int r0 = gm0 + mt * 16;
        const float s0 = g_sx[r0];
        const float s1 = g_sx[r0 + 8];
#pragma unroll
        for (int nt = 0; nt < 4; nt++) {
            const int c = gn0 + nt * 8;
            float2 v0 = make_float2(acc[mt][nt][0] * s0, acc[mt][nt][1] * s0);
            float2 v1 = make_float2(acc[mt][nt][2] * s1, acc[mt][nt][3] * s1);
            *(float2*)&out[(size_t)r0 * DOUT + c] = v0;
            *(float2*)&out[(size_t)(r0 + 8) * DOUT + c] = v1;
        }
    }
}

// ---------------------------------------------------------------------------
extern "C" void kernel_launch(void* const* d_in, const int* in_sizes, int n_in,
                              void* d_out, int out_size) {
    (void)in_sizes; (void)n_in; (void)out_size;
    const float* x      = (const float*)d_in[0];
    const int*   w_int  = (const int*)d_in[1];
    const float* w_sc   = (const float*)d_in[2];
    const float* w_zp   = (const float*)d_in[3];
    float* out = (float*)d_out;

    cudaFuncSetAttribute(gemm_kernel, cudaFuncAttributeMaxDynamicSharedMemorySize, SMEM_TOTAL);

    prep_kernel<<<QBLOCKS + WBLOCKS, 256>>>((const float4*)x, (const int4*)w_int, w_sc, w_zp);
    gemm_kernel<<<dim3(DOUT / BN, MTOT / BM), 256, SMEM_TOTAL>>>(out);
}